// round 2
// baseline (speedup 1.0000x reference)
#include <cuda_runtime.h>
#include <math.h>

#define N_SLOTS 16384
#define MD      512
#define CTRL    1024
#define OUTF    (3*MD + 6)   // 1542
#define EPSF    1e-16f

// ---- scratch (device globals: no allocation allowed) ----
__device__ float g_o[OUTF];
__device__ float g_e[MD];
__device__ float g_a[MD];
__device__ float g_expwc[N_SLOTS];
__device__ float g_wp[N_SLOTS];
__device__ float g_partialB[2048];
__device__ float g_partialC[64];
__device__ float g_params[7];   // beta, g, s0, s1, s2, gamma, k_norm
__device__ float g_inv_sumexp;
__device__ float g_inv_sumwp;

__device__ __forceinline__ float softplusf(float x) {
    return x > 20.f ? x : log1pf(expf(x));
}

// ---- K1: o = emb @ W^T + b  (one warp per output row) ----
__global__ void k_proj(const float* __restrict__ emb,
                       const float* __restrict__ W,
                       const float* __restrict__ b) {
    int warp = threadIdx.x >> 5;
    int lane = threadIdx.x & 31;
    int row  = blockIdx.x * 4 + warp;
    if (row >= OUTF) return;
    const float4* W4 = (const float4*)(W + (size_t)row * CTRL);
    const float4* e4 = (const float4*)emb;
    float sum = 0.f;
#pragma unroll
    for (int j = 0; j < 8; j++) {
        float4 wv = W4[lane + 32*j];
        float4 ev = e4[lane + 32*j];
        sum += wv.x*ev.x + wv.y*ev.y + wv.z*ev.z + wv.w*ev.w;
    }
#pragma unroll
    for (int off = 16; off; off >>= 1) sum += __shfl_down_sync(0xffffffffu, sum, off);
    if (lane == 0) g_o[row] = sum + b[row];
}

// ---- K2: derived scalars + aligned copies of e,a (1 block, 512 threads) ----
__global__ void k_params() {
    __shared__ float red[512];
    int t = threadIdx.x;
    float v = g_o[t];
    red[t] = v * v;
    g_e[t] = g_o[MD + 6 + t];
    g_a[t] = g_o[2*MD + 6 + t];
    __syncthreads();
    for (int s = 256; s; s >>= 1) { if (t < s) red[t] += red[t+s]; __syncthreads(); }
    if (t == 0) {
        float knorm = sqrtf(red[0]);
        float beta  = softplusf(g_o[MD]);
        float gg    = 1.f / (1.f + expf(-g_o[MD+1]));
        float x0 = g_o[MD+2], x1 = g_o[MD+3], x2 = g_o[MD+4];
        float m  = fmaxf(x0, fmaxf(x1, x2));
        float e0 = expf(x0-m), e1 = expf(x1-m), e2 = expf(x2-m);
        float inv = 1.f / (e0 + e1 + e2);
        float gamma = 1.f + softplusf(g_o[MD+5]);
        g_params[0] = beta; g_params[1] = gg;
        g_params[2] = e0*inv; g_params[3] = e1*inv; g_params[4] = e2*inv;
        g_params[5] = gamma; g_params[6] = knorm;
    }
}

// ---- K3: cosine sim + exp(beta*sim), per-block partial sums (warp/row) ----
__global__ void k_sim(const float* __restrict__ mem) {
    __shared__ float sk[MD];
    __shared__ float wsum[8];
    int tid = threadIdx.x;
    for (int i = tid; i < MD; i += 256) sk[i] = g_o[i];
    __syncthreads();
    int wid = tid >> 5, lane = tid & 31;
    int row = blockIdx.x * 8 + wid;
    const float4* m4 = (const float4*)(mem + (size_t)row * MD);
    const float4* k4 = (const float4*)sk;
    float dot = 0.f, nrm = 0.f;
#pragma unroll
    for (int j = 0; j < 4; j++) {
        float4 mv = m4[lane + 32*j];
        float4 kv = k4[lane + 32*j];
        dot += mv.x*kv.x + mv.y*kv.y + mv.z*kv.z + mv.w*kv.w;
        nrm += mv.x*mv.x + mv.y*mv.y + mv.z*mv.z + mv.w*mv.w;
    }
#pragma unroll
    for (int off = 16; off; off >>= 1) {
        dot += __shfl_down_sync(0xffffffffu, dot, off);
        nrm += __shfl_down_sync(0xffffffffu, nrm, off);
    }
    if (lane == 0) {
        float denom = g_params[6] * sqrtf(nrm) + EPSF;
        // sim in [-1,1], beta modest: exp cannot overflow -> skip max pass
        float ex = expf(g_params[0] * dot / denom);
        g_expwc[row] = ex;
        wsum[wid] = ex;
    }
    __syncthreads();
    if (tid == 0) {
        float s = 0.f;
#pragma unroll
        for (int i = 0; i < 8; i++) s += wsum[i];
        g_partialB[blockIdx.x] = s;
    }
}

// ---- K4: deterministic reduce of 2048 partials ----
__global__ void k_sumexp() {
    __shared__ float red[1024];
    int t = threadIdx.x;
    red[t] = g_partialB[t] + g_partialB[t + 1024];
    __syncthreads();
    for (int s = 512; s; s >>= 1) { if (t < s) red[t] += red[t+s]; __syncthreads(); }
    if (t == 0) g_inv_sumexp = 1.f / red[0];
}

// ---- K5: interpolate + circular shift + sharpen ----
__global__ void k_shiftpow(const float* __restrict__ w_prev) {
    int i = blockIdx.x * 256 + threadIdx.x;
    float gg = g_params[1], s0 = g_params[2], s1 = g_params[3],
          s2 = g_params[4], gamma = g_params[5];
    float ise = g_inv_sumexp;
    float omg = 1.f - gg;
    int im = (i == 0) ? N_SLOTS-1 : i-1;
    int ip = (i == N_SLOTS-1) ? 0 : i+1;
    float wgm = gg * g_expwc[im] * ise + omg * w_prev[im];
    float wgc = gg * g_expwc[i ] * ise + omg * w_prev[i ];
    float wgp = gg * g_expwc[ip] * ise + omg * w_prev[ip];
    float ws = s0*wgm + s1*wgc + s2*wgp;
    float wp = powf(ws + EPSF, gamma);
    g_wp[i] = wp;
    __shared__ float red[256];
    red[threadIdx.x] = wp;
    __syncthreads();
    for (int s = 128; s; s >>= 1) { if (threadIdx.x < s) red[threadIdx.x] += red[threadIdx.x+s]; __syncthreads(); }
    if (threadIdx.x == 0) g_partialC[blockIdx.x] = red[0];
}

// ---- K6: reduce 64 partials ----
__global__ void k_sumwp() {
    __shared__ float red[64];
    int t = threadIdx.x;
    red[t] = g_partialC[t];
    __syncthreads();
    for (int s = 32; s; s >>= 1) { if (t < s) red[t] += red[t+s]; __syncthreads(); }
    if (t == 0) g_inv_sumwp = 1.f / red[0];
}

// ---- K7: memory update + w output (2 rows per 256-thread block) ----
__global__ void k_update(const float* __restrict__ mem, float* __restrict__ out) {
    int tid = threadIdx.x;
    int row = blockIdx.x * 2 + (tid >> 7);
    int col = tid & 127;
    float wv = g_wp[row] * g_inv_sumwp;
    if (col == 0) out[row] = wv;
    const float4* m4 = (const float4*)(mem + (size_t)row * MD);
    const float4* e4 = (const float4*)g_e;
    const float4* a4 = (const float4*)g_a;
    float4* o4 = (float4*)(out + N_SLOTS + (size_t)row * MD);
    float4 m = m4[col], e = e4[col], a = a4[col];
    float4 r;
    r.x = m.x * (1.f - wv*e.x) + wv*a.x;
    r.y = m.y * (1.f - wv*e.y) + wv*a.y;
    r.z = m.z * (1.f - wv*e.z) + wv*a.z;
    r.w = m.w * (1.f - wv*e.w) + wv*a.w;
    o4[col] = r;
}

extern "C" void kernel_launch(void* const* d_in, const int* in_sizes, int n_in,
                              void* d_out, int out_size) {
    const float* emb    = (const float*)d_in[0];   // (1, 1024)
    const float* w_prev = (const float*)d_in[1];   // (1, 16384)
    const float* mem    = (const float*)d_in[2];   // (16384, 512)
    const float* W      = (const float*)d_in[3];   // (1542, 1024)
    const float* b      = (const float*)d_in[4];   // (1542,)
    float* out = (float*)d_out;                    // [w(16384) | new_memory(16384*512)]

    k_proj<<<(OUTF + 3) / 4, 128>>>(emb, W, b);
    k_params<<<1, 512>>>();
    k_sim<<<N_SLOTS / 8, 256>>>(mem);
    k_sumexp<<<1, 1024>>>();
    k_shiftpow<<<N_SLOTS / 256, 256>>>(w_prev);
    k_sumwp<<<1, 64>>>();
    k_update<<<N_SLOTS / 2, 256>>>(mem, out);
}